// round 11
// baseline (speedup 1.0000x reference)
#include <cuda_runtime.h>
#include <cuda_fp16.h>
#include <cstdint>

// LightGCN: out = 0.25*(X + h1 + h2 + h3), h_{k+1} = A h_k
// Pull-based CSR, fp16 gathers/intermediates, fp32 accumulation.
// R11: pull widened to 8 lanes/edge x uint4 (16B) slices — fewer
// warp-instructions per edge (the layers are issue-bound, not L2-bound).
// Build = R8 separate-kernel form (best measured).

#define N_NODES 100000
#define D_FEAT  64
#define MAX_E   1600000
#define SCAN_BS 1024
#define N_SCAN_BLOCKS ((N_NODES + SCAN_BS - 1) / SCAN_BS)   // 98

// Static scratch (no allocation allowed). deg self-restores each call.
__device__ __half g_hX[(size_t)N_NODES * D_FEAT];
__device__ __half g_h1[(size_t)N_NODES * D_FEAT];
__device__ __half g_h2[(size_t)N_NODES * D_FEAT];
__device__ int    g_deg[N_NODES];
__device__ int    g_exloc[N_NODES];
__device__ int    g_blockSums[N_SCAN_BLOCKS];
__device__ int    g_off[N_NODES + 1];
__device__ int    g_rank[MAX_E];
__device__ int2   g_sedge[MAX_E];

// ---- prep: fp32->fp16 convert of X + dst histogram (return value = rank) ----
__global__ void k_prep(const float* __restrict__ X, __half* __restrict__ hX,
                       const int* __restrict__ dst, int n8, int nE) {
    int i = blockIdx.x * blockDim.x + threadIdx.x;
    if (i < n8) {
        const float4* x4 = reinterpret_cast<const float4*>(X);
        float4 a = x4[2 * i];
        float4 b = x4[2 * i + 1];
        __half2 h0 = __floats2half2_rn(a.x, a.y);
        __half2 h1 = __floats2half2_rn(a.z, a.w);
        __half2 h2 = __floats2half2_rn(b.x, b.y);
        __half2 h3 = __floats2half2_rn(b.z, b.w);
        uint4 r;
        r.x = *reinterpret_cast<unsigned*>(&h0);
        r.y = *reinterpret_cast<unsigned*>(&h1);
        r.z = *reinterpret_cast<unsigned*>(&h2);
        r.w = *reinterpret_cast<unsigned*>(&h3);
        reinterpret_cast<uint4*>(hX)[i] = r;
    }
    if (i < nE) g_rank[i] = atomicAdd(&g_deg[dst[i]], 1);
}

// ---- per-block scan: block-local EXCLUSIVE prefix + block sums; resets deg ----
__global__ void k_scan_block(int n) {
    __shared__ int sh[SCAN_BS];
    int t = threadIdx.x;
    int i = blockIdx.x * SCAN_BS + t;
    int v = (i < n) ? g_deg[i] : 0;
    sh[t] = v;
    __syncthreads();
    for (int d = 1; d < SCAN_BS; d <<= 1) {
        int x = (t >= d) ? sh[t - d] : 0;
        __syncthreads();
        sh[t] += x;
        __syncthreads();
    }
    if (i < n) {
        g_exloc[i] = sh[t] - v;   // exclusive within block
        g_deg[i] = 0;             // self-restore for next replay
    }
    if (t == SCAN_BS - 1) g_blockSums[blockIdx.x] = sh[t];
}

// ---- finalize: recompute chunk base from the 98 block sums; write off ----
__global__ void k_finalize(int n, int nE) {
    __shared__ int s_base;
    int chunk = blockIdx.x >> 2;
    if (threadIdx.x < 32) {
        int acc = 0;
        for (int j = (int)threadIdx.x; j < chunk; j += 32) acc += g_blockSums[j];
        #pragma unroll
        for (int o = 16; o; o >>= 1) acc += __shfl_down_sync(0xffffffffu, acc, o);
        if (threadIdx.x == 0) s_base = acc;
    }
    __syncthreads();
    int i = blockIdx.x * 256 + threadIdx.x;
    if (i >= n) return;
    g_off[i] = g_exloc[i] + s_base;
    if (i == n - 1) g_off[n] = nE;
}

// ---- scatter: pure streaming, NO atomics ----
__global__ void k_scatter(const int* __restrict__ src,
                          const int* __restrict__ dst,
                          const float* __restrict__ ew, int nE) {
    int e = blockIdx.x * blockDim.x + threadIdx.x;
    if (e >= nE) return;
    int pos = g_off[dst[e]] + g_rank[e];
    g_sedge[pos] = make_int2(src[e], __float_as_int(ew[e]));
}

// ---------------- Pull SpMM: 8 lanes/edge, uint4 slices ----------------
// Warp = 4 groups of 8 lanes. Group g handles edges begin+g, stride 4.
// Lane c8 (0..7) owns features [8*c8, 8*c8+8) = one 16B uint4 of the 128B row.
// Final: combine the 4 groups with two shfl_xor stages (8, 16).

__device__ __forceinline__ void node_reduce8(const __half* __restrict__ Hin,
                                             int node, int c8, int grp,
                                             float acc[8]) {
    int begin = g_off[node], end = g_off[node + 1];
    #pragma unroll
    for (int i = 0; i < 8; i++) acc[i] = 0.f;
    for (int e = begin + grp; e < end; e += 4) {
        int2  p = g_sedge[e];                 // broadcast within the 8-lane group
        float w = __int_as_float(p.y);
        uint4 u = reinterpret_cast<const uint4*>(Hin + (size_t)p.x * D_FEAT)[c8];
        float2 f0 = __half22float2(*reinterpret_cast<__half2*>(&u.x));
        float2 f1 = __half22float2(*reinterpret_cast<__half2*>(&u.y));
        float2 f2 = __half22float2(*reinterpret_cast<__half2*>(&u.z));
        float2 f3 = __half22float2(*reinterpret_cast<__half2*>(&u.w));
        acc[0] += w * f0.x; acc[1] += w * f0.y;
        acc[2] += w * f1.x; acc[3] += w * f1.y;
        acc[4] += w * f2.x; acc[5] += w * f2.y;
        acc[6] += w * f3.x; acc[7] += w * f3.y;
    }
    #pragma unroll
    for (int i = 0; i < 8; i++) {
        acc[i] += __shfl_xor_sync(0xffffffffu, acc[i], 8);
        acc[i] += __shfl_xor_sync(0xffffffffu, acc[i], 16);
    }
}

__device__ __forceinline__ uint4 pack8_half(const float acc[8]) {
    __half2 h0 = __floats2half2_rn(acc[0], acc[1]);
    __half2 h1 = __floats2half2_rn(acc[2], acc[3]);
    __half2 h2 = __floats2half2_rn(acc[4], acc[5]);
    __half2 h3 = __floats2half2_rn(acc[6], acc[7]);
    uint4 u;
    u.x = *reinterpret_cast<unsigned*>(&h0);
    u.y = *reinterpret_cast<unsigned*>(&h1);
    u.z = *reinterpret_cast<unsigned*>(&h2);
    u.w = *reinterpret_cast<unsigned*>(&h3);
    return u;
}

// Intermediate layer: write fp16 only.
__global__ void k_pull_h(const __half* __restrict__ Hin,
                         __half* __restrict__ Hout) {
    int gwarp = (blockIdx.x * blockDim.x + threadIdx.x) >> 5;
    if (gwarp >= N_NODES) return;
    int lane = threadIdx.x & 31;
    int grp  = lane >> 3;
    int c8   = lane & 7;
    float acc[8];
    node_reduce8(Hin, gwarp, c8, grp, acc);
    if (grp == 0)
        reinterpret_cast<uint4*>(Hout + (size_t)gwarp * D_FEAT)[c8] = pack8_half(acc);
}

// Final layer fused with the mean: out = 0.25*(X + h1 + h2 + h3).
__global__ void k_pull_final_h(const __half* __restrict__ Hin,   // h2 (fp16)
                               const float* __restrict__ X,
                               const __half* __restrict__ H1,
                               float* __restrict__ out) {
    int gwarp = (blockIdx.x * blockDim.x + threadIdx.x) >> 5;
    if (gwarp >= N_NODES) return;
    int lane = threadIdx.x & 31;
    int grp  = lane >> 3;
    int c8   = lane & 7;
    float acc[8];
    node_reduce8(Hin, gwarp, c8, grp, acc);   // h3 slice
    if (grp == 0) {
        size_t rowf = (size_t)gwarp * D_FEAT + (c8 << 3);
        float4 xa = *reinterpret_cast<const float4*>(X + rowf);
        float4 xb = *reinterpret_cast<const float4*>(X + rowf + 4);
        uint4 u1 = reinterpret_cast<const uint4*>(H1  + (size_t)gwarp * D_FEAT)[c8];
        uint4 u2 = reinterpret_cast<const uint4*>(Hin + (size_t)gwarp * D_FEAT)[c8];
        float2 a0 = __half22float2(*reinterpret_cast<__half2*>(&u1.x));
        float2 a1 = __half22float2(*reinterpret_cast<__half2*>(&u1.y));
        float2 a2 = __half22float2(*reinterpret_cast<__half2*>(&u1.z));
        float2 a3 = __half22float2(*reinterpret_cast<__half2*>(&u1.w));
        float2 b0 = __half22float2(*reinterpret_cast<__half2*>(&u2.x));
        float2 b1 = __half22float2(*reinterpret_cast<__half2*>(&u2.y));
        float2 b2 = __half22float2(*reinterpret_cast<__half2*>(&u2.z));
        float2 b3 = __half22float2(*reinterpret_cast<__half2*>(&u2.w));
        float4 oa, ob;
        oa.x = 0.25f * (xa.x + a0.x + b0.x + acc[0]);
        oa.y = 0.25f * (xa.y + a0.y + b0.y + acc[1]);
        oa.z = 0.25f * (xa.z + a1.x + b1.x + acc[2]);
        oa.w = 0.25f * (xa.w + a1.y + b1.y + acc[3]);
        ob.x = 0.25f * (xb.x + a2.x + b2.x + acc[4]);
        ob.y = 0.25f * (xb.y + a2.y + b2.y + acc[5]);
        ob.z = 0.25f * (xb.z + a3.x + b3.x + acc[6]);
        ob.w = 0.25f * (xb.w + a3.y + b3.y + acc[7]);
        *reinterpret_cast<float4*>(out + rowf)     = oa;
        *reinterpret_cast<float4*>(out + rowf + 4) = ob;
    }
}

extern "C" void kernel_launch(void* const* d_in, const int* in_sizes, int n_in,
                              void* d_out, int out_size) {
    const float* X   = (const float*)d_in[0];
    const int*   src = (const int*)  d_in[1];
    const int*   dst = (const int*)  d_in[2];
    const float* ew  = (const float*)d_in[3];
    float* out = (float*)d_out;
    const int nE = in_sizes[1];

    __half* hX = nullptr;
    __half* h1 = nullptr;
    __half* h2 = nullptr;
    cudaGetSymbolAddress((void**)&hX, g_hX);
    cudaGetSymbolAddress((void**)&h1, g_h1);
    cudaGetSymbolAddress((void**)&h2, g_h2);

    const int TB = 256;
    const int n8       = N_NODES * D_FEAT / 8;
    const int prepN    = (nE > n8) ? nE : n8;
    const int gridPrep = (prepN + TB - 1) / TB;
    const int gridFin  = (N_NODES + 255) / 256;
    const int gridE    = (nE + TB - 1) / TB;
    const int gridPull = (N_NODES * 32 + TB - 1) / TB;   // warp per node

    // --- build dst-sorted CSR ---
    k_prep<<<gridPrep, TB>>>(X, hX, dst, n8, nE);
    k_scan_block<<<N_SCAN_BLOCKS, SCAN_BS>>>(N_NODES);
    k_finalize<<<gridFin, 256>>>(N_NODES, nE);
    k_scatter<<<gridE, TB>>>(src, dst, ew, nE);

    // --- 3 pull layers (8-lane/edge uint4 slices) ---
    k_pull_h<<<gridPull, TB>>>(hX, h1);
    k_pull_h<<<gridPull, TB>>>(h1, h2);
    k_pull_final_h<<<gridPull, TB>>>(h2, X, h1, out);
}